// round 7
// baseline (speedup 1.0000x reference)
#include <cuda_runtime.h>
#include <cuda_fp16.h>
#include <cstdint>

// ---------------------------------------------------------------------------
// out[M,N] = segment_mean(gather(cf, member_idx), segment_ids) @ W + b
// R7: FUSED kernel. Per CTA: phase 1 computes the means of its 128 cells
// straight into a 64KB smem fp16 A-tile (no gmem round-trip), phase 2 runs
// the full-K GEMM over 4 N-tiles with double-buffered B chunks. Gather
// latency of one CTA hides under tensor work of the co-resident CTA.
// Prelude kernels: starts[] (segment boundaries) + W transpose->fp16.
// Shapes: K=256, N=512 (layout constants assume these).
// ---------------------------------------------------------------------------

__device__ __half g_b[512 * 256];   // [N][K] fp16 (W transposed)
__device__ int g_starts[65600];     // zero-init; [c]=first member of cell c

// ---------------------------------------------------------------------------
// PTX helpers (baseline sm_80 features — safe through compute_103 PTX)
// ---------------------------------------------------------------------------
__device__ __forceinline__ uint32_t smem_u32(const void* p) {
    uint32_t a;
    asm("{ .reg .u64 t; cvta.to.shared.u64 t, %1; cvt.u32.u64 %0, t; }"
        : "=r"(a) : "l"(p));
    return a;
}

#define CP16(dst, src) \
    asm volatile("cp.async.cg.shared.global [%0], [%1], 16;" \
                 :: "r"(dst), "l"(src) : "memory")
#define CP_COMMIT() asm volatile("cp.async.commit_group;" ::: "memory")
#define CP_WAIT1()  asm volatile("cp.async.wait_group 1;" ::: "memory")
#define CP_WAIT0()  asm volatile("cp.async.wait_group 0;" ::: "memory")

#define LDM4(r, a) \
    asm volatile("ldmatrix.sync.aligned.m8n8.x4.shared.b16 {%0,%1,%2,%3}, [%4];" \
                 : "=r"((r)[0]), "=r"((r)[1]), "=r"((r)[2]), "=r"((r)[3]) \
                 : "r"(a))

#define MMA_F16(d, a, b0, b1) \
    asm volatile("mma.sync.aligned.m16n8k16.row.col.f32.f16.f16.f32 " \
                 "{%0,%1,%2,%3}, {%4,%5,%6,%7}, {%8,%9}, {%0,%1,%2,%3};" \
                 : "+f"((d)[0]), "+f"((d)[1]), "+f"((d)[2]), "+f"((d)[3]) \
                 : "r"((a)[0]), "r"((a)[1]), "r"((a)[2]), "r"((a)[3]), \
                   "r"(b0), "r"(b1))

// ---------------------------------------------------------------------------
// Kernel 0: segment starts
// ---------------------------------------------------------------------------
__global__ void starts_kernel(const int* __restrict__ seg, int num_members, int num_cells) {
    int i = blockIdx.x * blockDim.x + threadIdx.x;
    if (i > num_members) return;
    int cur  = (i < num_members) ? seg[i] : num_cells;
    int prev = (i > 0) ? seg[i - 1] : -1;
    for (int c = prev + 1; c <= cur; c++) g_starts[c] = i;
}

// ---------------------------------------------------------------------------
// Kernel 1: W prepack -> [N][K] fp16 (transposed for mma.sync col-major B)
// ---------------------------------------------------------------------------
__global__ void prepw_kernel(const float* __restrict__ W, int K, int N) {
    int idx = blockIdx.x * blockDim.x + threadIdx.x;
    if (idx >= K * N) return;
    int n = idx / K, k = idx - n * K;
    g_b[(size_t)n * K + k] = __float2half_rn(W[(size_t)k * N + n]);
}

// ---------------------------------------------------------------------------
// Fused kernel: phase 1 mean -> smem A-tile [128 x 256] fp16 (512B rows,
// 16B chunks swizzled ch_low3 ^= row&7); phase 2 GEMM over 4 N-tiles with
// double-buffered B chunks [128 x 64] fp16 (128B rows, same swizzle).
// smem: A 64KB @0, B 2x16KB @64KB = 96KB -> 2 CTAs/SM.
// 8 warps: 4M x 2N, warp tile 32x64.
// ---------------------------------------------------------------------------
#define SM_A    0u
#define SM_B    65536u
#define B_BUF   16384u
#define SMEM_TOTAL (65536u + 2u * 16384u)

__global__ __launch_bounds__(256, 2)
void fused_kernel(const float4* __restrict__ cf4,
                  const int* __restrict__ midx,
                  const float* __restrict__ bias,
                  float* __restrict__ C,
                  int M, int N, int K) {
    extern __shared__ char smem[];
    const uint32_t sb = smem_u32(smem);
    const int tid = threadIdx.x;
    const int wid = tid >> 5, lane = tid & 31;
    const int bm = blockIdx.x * 128;
    const int K4 = K >> 2;                 // float4 per cf row (64)

    // ---- B loader assignments (4 (row,chunk) slots per thread) ----
    int brow[4], bch[4];
    uint32_t bdst[4];
#pragma unroll
    for (int i = 0; i < 4; i++) {
        int idx = i * 256 + tid;
        brow[i] = idx >> 3;                // 0..127 (B tile row = N row)
        bch[i]  = idx & 7;                 // 16B chunk within 128B
        bdst[i] = (uint32_t)(brow[i] * 128 + ((bch[i] ^ (brow[i] & 7)) << 4));
    }
    const char* gB = (const char*)g_b;     // row stride = K*2 = 512B

    // issue B loads for t=0 and t=1 (nt=0, kc=0/1) before phase 1
#pragma unroll
    for (int pre = 0; pre < 2; pre++) {
        uint32_t dst = sb + SM_B + (uint32_t)pre * B_BUF;
#pragma unroll
        for (int i = 0; i < 4; i++)
            CP16(dst + bdst[i], gB + (size_t)brow[i] * 512 + pre * 128 + bch[i] * 16);
        CP_COMMIT();
    }

    // ---- phase 1: means of cells [bm, bm+128) -> smem A-tile ----
    // warp w handles rows w*16 .. w*16+15; lane owns halves [lane*8, +8).
#pragma unroll 1
    for (int i = 0; i < 16; i++) {
        const int r = (wid << 4) + i;
        const int c = bm + r;
        const int start = __ldg(&g_starts[c]);
        const int end   = __ldg(&g_starts[c + 1]);

        float4 p0a = make_float4(0.f,0.f,0.f,0.f), p0b = p0a;
        float4 p1a = p0a, p1b = p0a;

        const int base = 2 * lane;         // float4 slot within row
        int j = start;
        for (; j + 4 <= end; j += 4) {
            int i0 = __ldg(&midx[j])     * K4;
            int i1 = __ldg(&midx[j + 1]) * K4;
            int i2 = __ldg(&midx[j + 2]) * K4;
            int i3 = __ldg(&midx[j + 3]) * K4;
            float4 v00 = cf4[(size_t)i0 + base], v01 = cf4[(size_t)i0 + base + 1];
            float4 v10 = cf4[(size_t)i1 + base], v11 = cf4[(size_t)i1 + base + 1];
            float4 v20 = cf4[(size_t)i2 + base], v21 = cf4[(size_t)i2 + base + 1];
            float4 v30 = cf4[(size_t)i3 + base], v31 = cf4[(size_t)i3 + base + 1];
            p0a.x += v00.x; p0a.y += v00.y; p0a.z += v00.z; p0a.w += v00.w;
            p0b.x += v10.x; p0b.y += v10.y; p0b.z += v10.z; p0b.w += v10.w;
            p0a.x += v20.x; p0a.y += v20.y; p0a.z += v20.z; p0a.w += v20.w;
            p0b.x += v30.x; p0b.y += v30.y; p0b.z += v30.z; p0b.w += v30.w;
            p1a.x += v01.x; p1a.y += v01.y; p1a.z += v01.z; p1a.w += v01.w;
            p1b.x += v11.x; p1b.y += v11.y; p1b.z += v11.z; p1b.w += v11.w;
            p1a.x += v21.x; p1a.y += v21.y; p1a.z += v21.z; p1a.w += v21.w;
            p1b.x += v31.x; p1b.y += v31.y; p1b.z += v31.z; p1b.w += v31.w;
        }
        for (; j < end; j++) {
            int i0 = __ldg(&midx[j]) * K4;
            float4 v00 = cf4[(size_t)i0 + base], v01 = cf4[(size_t)i0 + base + 1];
            p0a.x += v00.x; p0a.y += v00.y; p0a.z += v00.z; p0a.w += v00.w;
            p1a.x += v01.x; p1a.y += v01.y; p1a.z += v01.z; p1a.w += v01.w;
        }

        float inv = 1.0f / fmaxf((float)(end - start), 1.0f);
        __half2 h0 = __floats2half2_rn((p0a.x + p0b.x) * inv, (p0a.y + p0b.y) * inv);
        __half2 h1 = __floats2half2_rn((p0a.z + p0b.z) * inv, (p0a.w + p0b.w) * inv);
        __half2 h2 = __floats2half2_rn((p1a.x + p1b.x) * inv, (p1a.y + p1b.y) * inv);
        __half2 h3 = __floats2half2_rn((p1a.z + p1b.z) * inv, (p1a.w + p1b.w) * inv);
        uint4 pk;
        pk.x = *(uint32_t*)&h0; pk.y = *(uint32_t*)&h1;
        pk.z = *(uint32_t*)&h2; pk.w = *(uint32_t*)&h3;
        // chunk = lane; swizzle low 3 bits with row
        uint32_t cs = (uint32_t)((lane & 24) | ((lane ^ r) & 7));
        *(uint4*)(smem + SM_A + r * 512 + cs * 16) = pk;
    }
    __syncthreads();

    // ---- phase 2: GEMM over 4 N-tiles, K chunks of 64, double-buffered B ----
    const int wm = wid & 3;                // warp row -> 32 rows
    const int wn = wid >> 2;               // warp col -> 64 cols
    const int a_r = (lane & 15);
    const int a_cadd = (lane >> 4);
    const int b_r = (lane & 7) + ((lane >> 4) << 3);
    const int b_cadd = ((lane >> 3) & 1);

    const int NKC = K >> 6;                // 4 k-chunks
    const int NT  = (N >> 7) * NKC;        // 16 total steps

    float acc[2][8][4];

    for (int t = 0; t < NT; t++) {
        const int kc = t & (NKC - 1);
        const int nt = t >> 2;
        const uint32_t buf = sb + SM_B + (uint32_t)(t & 1) * B_BUF;

        if (t < NT - 1) { CP_WAIT1(); } else { CP_WAIT0(); }
        __syncthreads();

        if (kc == 0) {
#pragma unroll
            for (int g = 0; g < 2; g++)
#pragma unroll
                for (int n = 0; n < 8; n++)
#pragma unroll
                    for (int q = 0; q < 4; q++) acc[g][n][q] = 0.f;
        }

        // compute: 4 k16 steps on this (nt, kc)
#pragma unroll
        for (int s = 0; s < 4; s++) {
            const int s16 = kc * 4 + s;    // global k16 step for A
            uint32_t af[2][4];
#pragma unroll
            for (int g = 0; g < 2; g++) {
                int row = wm * 32 + g * 16 + a_r;
                int ch  = 2 * s16 + a_cadd;           // 0..31
                uint32_t chs = (uint32_t)((ch & 24) | ((ch ^ row) & 7));
                LDM4(af[g], sb + SM_A + row * 512 + chs * 16);
            }
            uint32_t bf[4][4];
#pragma unroll
            for (int h = 0; h < 4; h++) {
                int row = wn * 64 + h * 16 + b_r;
                int ch  = 2 * s + b_cadd;             // 0..7
                LDM4(bf[h], buf + row * 128 + ((ch ^ (row & 7)) << 4));
            }
#pragma unroll
            for (int h = 0; h < 4; h++)
#pragma unroll
                for (int g = 0; g < 2; g++) {
                    MMA_F16(acc[g][h * 2],     af[g], bf[h][0], bf[h][1]);
                    MMA_F16(acc[g][h * 2 + 1], af[g], bf[h][2], bf[h][3]);
                }
        }
        __syncthreads();

        // prefetch B for step t+2 into the buffer just freed
        if (t + 2 < NT) {
            const int t2 = t + 2;
            const int kc2 = t2 & (NKC - 1), nt2 = t2 >> 2;
            const uint32_t dst = sb + SM_B + (uint32_t)(t2 & 1) * B_BUF;
            const char* gsrc = gB + (size_t)(nt2 * 128) * 512 + kc2 * 128;
#pragma unroll
            for (int i = 0; i < 4; i++)
                CP16(dst + bdst[i], gsrc + (size_t)brow[i] * 512 + bch[i] * 16);
        }
        CP_COMMIT();

        // epilogue at the end of each N-tile
        if (kc == NKC - 1) {
            const int colb = nt * 128 + wn * 64;
#pragma unroll
            for (int g = 0; g < 2; g++) {
                int row0 = bm + wm * 32 + g * 16 + (lane >> 2);
                int row1 = row0 + 8;
#pragma unroll
                for (int n = 0; n < 8; n++) {
                    int col = colb + n * 8 + (lane & 3) * 2;
                    float2 bb = *(const float2*)&bias[col];
                    if (row0 < M) {
                        float2 o = make_float2(acc[g][n][0] + bb.x, acc[g][n][1] + bb.y);
                        *(float2*)&C[(size_t)row0 * N + col] = o;
                    }
                    if (row1 < M) {
                        float2 o = make_float2(acc[g][n][2] + bb.x, acc[g][n][3] + bb.y);
                        *(float2*)&C[(size_t)row1 * N + col] = o;
                    }
                }
            }
        }
    }
}

// ---------------------------------------------------------------------------
// Launch
// ---------------------------------------------------------------------------
extern "C" void kernel_launch(void* const* d_in, const int* in_sizes, int n_in,
                              void* d_out, int out_size) {
    const float* cf   = (const float*)d_in[0];
    const int* midx   = (const int*)d_in[1];
    const int* seg    = (const int*)d_in[2];
    const float* W    = (const float*)d_in[4];
    const float* bias = (const float*)d_in[5];
    float* out = (float*)d_out;

    const int N = in_sizes[5];           // 512
    const int K = in_sizes[4] / N;       // 256
    const int M = out_size / N;          // 50000
    const int num_members = in_sizes[1]; // 400000

    cudaFuncSetAttribute(fused_kernel,
                         cudaFuncAttributeMaxDynamicSharedMemorySize,
                         (int)SMEM_TOTAL);

    starts_kernel<<<(num_members + 256) / 256, 256>>>(seg, num_members, M);
    prepw_kernel<<<(K * N + 255) / 256, 256>>>(W, K, N);

    fused_kernel<<<(M + 127) / 128, 256, SMEM_TOTAL>>>(
        (const float4*)cf, midx, bias, out, M, N, K);
}

// round 8
// speedup vs baseline: 1.0719x; 1.0719x over previous
#include <cuda_runtime.h>
#include <cuda_fp16.h>
#include <cstdint>

// ---------------------------------------------------------------------------
// out[M,N] = segment_mean(gather(cf, member_idx), segment_ids) @ W + b
// R8: revert to R6 split structure (fusion regressed). Mean kernel gets
// warp-broadcast index batching (one coalesced index load + shfl, 4-deep
// independent row gathers) instead of serialized per-member index loads.
// GEMM unchanged from R6 (fp16 mma.sync, BK=64, 3-stage cp.async).
// ---------------------------------------------------------------------------

#define MAX_ROWS_PAD 65664          // multiple of 128, >= padded M
#define AK 256                      // K (input_dim) capacity

// Zero-initialized scratch. Rows >= M never written -> stay zero (no guards).
__device__ __half g_a[(size_t)MAX_ROWS_PAD * AK];
__device__ __half g_b[1024 * 512];          // [N][K] (W transposed)
__device__ int g_starts[65600];

// ---------------------------------------------------------------------------
// PTX helpers (baseline sm_80 features — safe through compute_103 PTX)
// ---------------------------------------------------------------------------
__device__ __forceinline__ uint32_t smem_u32(const void* p) {
    uint32_t a;
    asm("{ .reg .u64 t; cvta.to.shared.u64 t, %1; cvt.u32.u64 %0, t; }"
        : "=r"(a) : "l"(p));
    return a;
}

#define CP16(dst, src) \
    asm volatile("cp.async.cg.shared.global [%0], [%1], 16;" \
                 :: "r"(dst), "l"(src) : "memory")
#define CP_COMMIT() asm volatile("cp.async.commit_group;" ::: "memory")
#define CP_WAIT1()  asm volatile("cp.async.wait_group 1;" ::: "memory")

#define LDM4(r, a) \
    asm volatile("ldmatrix.sync.aligned.m8n8.x4.shared.b16 {%0,%1,%2,%3}, [%4];" \
                 : "=r"((r)[0]), "=r"((r)[1]), "=r"((r)[2]), "=r"((r)[3]) \
                 : "r"(a))

#define MMA_F16(d, a, b0, b1) \
    asm volatile("mma.sync.aligned.m16n8k16.row.col.f32.f16.f16.f32 " \
                 "{%0,%1,%2,%3}, {%4,%5,%6,%7}, {%8,%9}, {%0,%1,%2,%3};" \
                 : "+f"((d)[0]), "+f"((d)[1]), "+f"((d)[2]), "+f"((d)[3]) \
                 : "r"((a)[0]), "r"((a)[1]), "r"((a)[2]), "r"((a)[3]), \
                   "r"(b0), "r"(b1))

#define ACC4(a, v) { (a).x += (v).x; (a).y += (v).y; (a).z += (v).z; (a).w += (v).w; }

// ---------------------------------------------------------------------------
// Kernel 0: segment starts (shfl_up to halve loads)
// ---------------------------------------------------------------------------
__global__ void starts_kernel(const int* __restrict__ seg, int num_members, int num_cells) {
    int i = blockIdx.x * blockDim.x + threadIdx.x;
    if (i > num_members) return;
    int cur  = (i < num_members) ? __ldg(&seg[i]) : num_cells;
    int prev = __shfl_up_sync(0xFFFFFFFFu, cur, 1);
    if ((threadIdx.x & 31) == 0)
        prev = (i > 0) ? __ldg(&seg[i - 1]) : -1;
    if (i == num_members) prev = (i > 0) ? __ldg(&seg[i - 1]) : -1;
    for (int c = prev + 1; c <= cur; c++) g_starts[c] = i;
}

// ---------------------------------------------------------------------------
// Kernel 1: segment mean -> fp16. Block 256 thr = 4 cells, 2 warps per cell.
// Warp half h (0/1) of a cell owns float4 chunks [h*32+lane]. Indices are
// fetched 32-at-a-time with ONE coalesced load then shfl-broadcast; row
// gathers run 4 deep with no dependent index load in the chain.
// ---------------------------------------------------------------------------
__global__ void mean_kernel(const float4* __restrict__ cf4,
                            const int* __restrict__ midx,
                            int K4, int M) {
    const int wid  = threadIdx.x >> 5;        // 0..7
    const int lane = threadIdx.x & 31;
    const int c    = blockIdx.x * 4 + (wid >> 1);   // cell
    const int half = wid & 1;                 // which 32-chunk half of the row
    if (c >= M) return;

    const int start = __ldg(&g_starts[c]);
    const int end   = __ldg(&g_starts[c + 1]);
    const int cnt   = end - start;
    const int chunk = half * 32 + lane;       // float4 chunk owned by lane

    float4 a0 = make_float4(0.f, 0.f, 0.f, 0.f);
    float4 a1 = a0, a2 = a0, a3 = a0;

    for (int jb = 0; jb < cnt; jb += 32) {
        int myidx = 0;
        if (jb + lane < cnt) myidx = __ldg(&midx[start + jb + lane]);
        const int bn = min(32, cnt - jb);
        int u = 0;
        for (; u + 4 <= bn; u += 4) {
            int i0 = __shfl_sync(0xFFFFFFFFu, myidx, u);
            int i1 = __shfl_sync(0xFFFFFFFFu, myidx, u + 1);
            int i2 = __shfl_sync(0xFFFFFFFFu, myidx, u + 2);
            int i3 = __shfl_sync(0xFFFFFFFFu, myidx, u + 3);
            float4 v0 = cf4[(size_t)i0 * K4 + chunk];
            float4 v1 = cf4[(size_t)i1 * K4 + chunk];
            float4 v2 = cf4[(size_t)i2 * K4 + chunk];
            float4 v3 = cf4[(size_t)i3 * K4 + chunk];
            ACC4(a0, v0); ACC4(a1, v1); ACC4(a2, v2); ACC4(a3, v3);
        }
        for (; u < bn; u++) {
            int i0 = __shfl_sync(0xFFFFFFFFu, myidx, u);
            float4 v0 = cf4[(size_t)i0 * K4 + chunk];
            ACC4(a0, v0);
        }
    }

    const float inv = 1.0f / fmaxf((float)cnt, 1.0f);
    __half2 h0 = __floats2half2_rn((a0.x + a1.x + a2.x + a3.x) * inv,
                                   (a0.y + a1.y + a2.y + a3.y) * inv);
    __half2 h1 = __floats2half2_rn((a0.z + a1.z + a2.z + a3.z) * inv,
                                   (a0.w + a1.w + a2.w + a3.w) * inv);
    uint2 pk;
    pk.x = *(uint32_t*)&h0;
    pk.y = *(uint32_t*)&h1;
    ((uint2*)g_a)[(size_t)c * K4 + chunk] = pk;   // coalesced per warp
}

// ---------------------------------------------------------------------------
// Kernel 2: W prepack -> [N][K] fp16 via smem-tiled transpose (coalesced R/W)
// Block (32,8), tile 32x32. grid (K/32, N/32).
// ---------------------------------------------------------------------------
__global__ void prepw_kernel(const float* __restrict__ W, int K, int N) {
    __shared__ float t[32][33];
    const int kb = blockIdx.x * 32, nb = blockIdx.y * 32;
    const int tx = threadIdx.x, ty = threadIdx.y;
#pragma unroll
    for (int i = 0; i < 4; i++)
        t[ty + i * 8][tx] = W[(size_t)(kb + ty + i * 8) * N + nb + tx];
    __syncthreads();
#pragma unroll
    for (int i = 0; i < 4; i++)
        g_b[(size_t)(nb + ty + i * 8) * K + kb + tx] =
            __float2half_rn(t[tx][ty + i * 8]);
}

// ---------------------------------------------------------------------------
// Kernel 3: fp16 mma.sync GEMM (unchanged from R6).
// CTA tile 128x128, BK=64, 256 thr = 8 warps (4M x 2N), warp tile 32x64.
// Smem rows 128B (64 fp16), swizzle ch^=(row&7). 3 stages x 32KB.
// ---------------------------------------------------------------------------
#define STAGE_BYTES 32768u
#define SEC_BYTES   16384u
#define NSTAGE      3

__global__ __launch_bounds__(256, 2)
void gemm_mma_kernel(const float* __restrict__ bias, float* __restrict__ C,
                     int M, int N, int K) {
    extern __shared__ char smem[];
    const uint32_t sb = smem_u32(smem);
    const int tid  = threadIdx.x;
    const int wid  = tid >> 5, lane = tid & 31;
    const int wm   = wid & 3;
    const int wn   = wid >> 2;
    const int bm   = blockIdx.x * 128, bn = blockIdx.y * 128;
    const size_t rowb = (size_t)K * 2;

    const char* pA = (const char*)g_a + (size_t)bm * rowb;
    const char* pB = (const char*)g_b + (size_t)bn * rowb;

    uint32_t sdst[4];
    int lrow[4], lch[4];
#pragma unroll
    for (int i = 0; i < 4; i++) {
        int idx = i * 256 + tid;
        lrow[i] = idx >> 3;
        lch[i]  = idx & 7;
        sdst[i] = (uint32_t)(lrow[i] * 128 + ((lch[i] ^ (lrow[i] & 7)) << 4));
    }

    float acc[2][8][4];
#pragma unroll
    for (int g = 0; g < 2; g++)
#pragma unroll
        for (int n = 0; n < 8; n++)
#pragma unroll
            for (int j = 0; j < 4; j++) acc[g][n][j] = 0.f;

    const int a_r = (lane & 15);
    const int a_cadd = (lane >> 4);
    const int b_r = (lane & 7) + ((lane >> 4) << 3);
    const int b_cadd = ((lane >> 3) & 1);

    const int nit = K >> 6;

#pragma unroll
    for (int pre = 0; pre < 2; pre++) {
        const uint32_t sbase = sb + (uint32_t)pre * STAGE_BYTES;
        const size_t kt = (size_t)pre * 128;
#pragma unroll
        for (int i = 0; i < 4; i++) {
            CP16(sbase + sdst[i],             pA + (size_t)lrow[i] * rowb + kt + lch[i] * 16);
            CP16(sbase + SEC_BYTES + sdst[i], pB + (size_t)lrow[i] * rowb + kt + lch[i] * 16);
        }
        CP_COMMIT();
    }

    for (int it = 0; it < nit; it++) {
        const uint32_t stg = sb + (uint32_t)(it % NSTAGE) * STAGE_BYTES;
        CP_WAIT1();
        __syncthreads();

        if (it + 2 < nit) {
            const uint32_t sbase = sb + (uint32_t)((it + 2) % NSTAGE) * STAGE_BYTES;
            const size_t kt = (size_t)(it + 2) * 128;
#pragma unroll
            for (int i = 0; i < 4; i++) {
                CP16(sbase + sdst[i],             pA + (size_t)lrow[i] * rowb + kt + lch[i] * 16);
                CP16(sbase + SEC_BYTES + sdst[i], pB + (size_t)lrow[i] * rowb + kt + lch[i] * 16);
            }
            CP_COMMIT();
        } else {
            CP_COMMIT();
        }

#pragma unroll
        for (int s = 0; s < 4; s++) {
            uint32_t af[2][4];
#pragma unroll
            for (int g = 0; g < 2; g++) {
                int row = wm * 32 + g * 16 + a_r;
                int ch  = s * 2 + a_cadd;
                LDM4(af[g], stg + row * 128 + ((ch ^ (row & 7)) << 4));
            }
            uint32_t bf[4][4];
#pragma unroll
            for (int h = 0; h < 4; h++) {
                int row = wn * 64 + h * 16 + b_r;
                int ch  = s * 2 + b_cadd;
                LDM4(bf[h], stg + SEC_BYTES + row * 128 + ((ch ^ (row & 7)) << 4));
            }
#pragma unroll
            for (int h = 0; h < 4; h++)
#pragma unroll
                for (int g = 0; g < 2; g++) {
                    MMA_F16(acc[g][h * 2],     af[g], bf[h][0], bf[h][1]);
                    MMA_F16(acc[g][h * 2 + 1], af[g], bf[h][2], bf[h][3]);
                }
        }
        __syncthreads();
    }

#pragma unroll
    for (int g = 0; g < 2; g++) {
        int row0 = bm + wm * 32 + g * 16 + (lane >> 2);
        int row1 = row0 + 8;
#pragma unroll
        for (int n = 0; n < 8; n++) {
            int col = bn + wn * 64 + n * 8 + (lane & 3) * 2;
            float2 bb = *(const float2*)&bias[col];
            if (row0 < M) {
                float2 o = make_float2(acc[g][n][0] + bb.x, acc[g][n][1] + bb.y);
                *(float2*)&C[(size_t)row0 * N + col] = o;
            }
            if (row1 < M) {
                float2 o = make_float2(acc[g][n][2] + bb.x, acc[g][n][3] + bb.y);
                *(float2*)&C[(size_t)row1 * N + col] = o;
            }
        }
    }
}

// ---------------------------------------------------------------------------
// Launch
// ---------------------------------------------------------------------------
extern "C" void kernel_launch(void* const* d_in, const int* in_sizes, int n_in,
                              void* d_out, int out_size) {
    const float* cf   = (const float*)d_in[0];
    const int* midx   = (const int*)d_in[1];
    const int* seg    = (const int*)d_in[2];
    const float* W    = (const float*)d_in[4];
    const float* bias = (const float*)d_in[5];
    float* out = (float*)d_out;

    const int N = in_sizes[5];           // 512
    const int K = in_sizes[4] / N;       // 256
    const int M = out_size / N;          // 50000
    const int num_members = in_sizes[1]; // 400000
    const int K4 = K / 4;

    cudaFuncSetAttribute(gemm_mma_kernel,
                         cudaFuncAttributeMaxDynamicSharedMemorySize,
                         (int)(NSTAGE * STAGE_BYTES));

    starts_kernel<<<(num_members + 256) / 256, 256>>>(seg, num_members, M);
    dim3 tb(32, 8), tg(K / 32, N / 32);
    prepw_kernel<<<tg, tb>>>(W, K, N);
    mean_kernel<<<(M + 3) / 4, 256>>>((const float4*)cf, midx, K4, M);

    dim3 grid((M + 127) / 128, N / 128);
    gemm_mma_kernel<<<grid, 256, NSTAGE * STAGE_BYTES>>>(bias, out, M, N, K);
}